// round 2
// baseline (speedup 1.0000x reference)
#include <cuda_runtime.h>
#include <math.h>
#include <stdint.h>

// Fixed problem geometry (max sizes; actual n/e derived from in_sizes)
#define MAXN 100000
#define MAXE 3200000
#define DD   256          // size_in (output dim of layer 1)
#define KK2  512          // 2*D (input dim of layer 1)

// ---------------- scratch (device globals: no cudaMalloc allowed) -------------
__device__ float g_h0[(size_t)MAXN * DD];   // x @ W1
__device__ float g_h1[(size_t)MAXN * DD];   // tanh(agg(h0)+b1)
__device__ float g_y0[MAXN];                // h1 @ W2
__device__ int   g_deg[MAXN];
__device__ float g_dinv[MAXN];
__device__ int   g_rowptr[MAXN + 1];
__device__ int   g_cur[MAXN];
__device__ int   g_src[MAXE + MAXN];        // CSR neighbor sources (incl. self loops)
__device__ float g_w[MAXE + MAXN];          // per-entry normalized weight
__device__ int   g_blksum[256];
__device__ float g_norm;

// ---------------- setup kernels ----------------------------------------------
__global__ void k_init(int n) {
    int i = blockIdx.x * blockDim.x + threadIdx.x;
    if (i < n) g_deg[i] = 1;               // self-loop contributes 1 to degree
    if (i == 0) g_norm = 0.f;
}

__global__ void k_count(const int* __restrict__ col, int e) {
    int i = blockIdx.x * blockDim.x + threadIdx.x;
    if (i < e) atomicAdd(&g_deg[col[i]], 1);
}

__global__ void k_dinv(int n) {
    int i = blockIdx.x * blockDim.x + threadIdx.x;
    if (i < n) g_dinv[i] = rsqrtf((float)g_deg[i]);
}

// inclusive block scan of g_deg -> g_rowptr[i+1] (local), block totals -> g_blksum
__global__ void k_scan1(int n) {
    __shared__ int sh[1024];
    int i = blockIdx.x * 1024 + threadIdx.x;
    int v = (i < n) ? g_deg[i] : 0;
    sh[threadIdx.x] = v;
    __syncthreads();
    for (int off = 1; off < 1024; off <<= 1) {
        int t = (threadIdx.x >= off) ? sh[threadIdx.x - off] : 0;
        __syncthreads();
        sh[threadIdx.x] += t;
        __syncthreads();
    }
    if (i < n) g_rowptr[i + 1] = sh[threadIdx.x];
    if (threadIdx.x == 1023) g_blksum[blockIdx.x] = sh[1023];
}

__global__ void k_scan2(int nb) {
    if (threadIdx.x == 0 && blockIdx.x == 0) {
        int run = 0;
        for (int b = 0; b < nb; b++) { int t = g_blksum[b]; g_blksum[b] = run; run += t; }
    }
}

__global__ void k_scan3(int n) {
    int i = blockIdx.x * blockDim.x + threadIdx.x;
    if (i < n) g_rowptr[i + 1] += g_blksum[i >> 10];
    if (i == 0) g_rowptr[0] = 0;
}

// pre-insert self loop at segment head; cursor starts just after it
__global__ void k_cur(int n) {
    int i = blockIdx.x * blockDim.x + threadIdx.x;
    if (i < n) {
        int p = g_rowptr[i];
        float di = g_dinv[i];
        g_src[p] = i;
        g_w[p]   = di * di;
        g_cur[i] = p + 1;
    }
}

__global__ void k_fill(const int* __restrict__ row, const int* __restrict__ col, int e) {
    int i = blockIdx.x * blockDim.x + threadIdx.x;
    if (i < e) {
        int r = row[i], c = col[i];
        int p = atomicAdd(&g_cur[c], 1);
        g_src[p] = r;
        g_w[p]   = g_dinv[r] * g_dinv[c];
    }
}

// ---------------- GEMM1: g_h0 = x @ W1  (M x 512) @ (512 x 256) ---------------
#define BM 128
#define BN 128
#define BK 8
__global__ __launch_bounds__(256) void k_gemm1(const float* __restrict__ A,
                                               const float* __restrict__ B, int M) {
    __shared__ float As[BK][BM + 4];
    __shared__ float Bs[BK][BN + 4];
    int tid = threadIdx.x;
    int tr = tid >> 4;            // 0..15
    int tc = tid & 15;            // 0..15
    int rowBase = blockIdx.y * BM;
    int colBase = blockIdx.x * BN;

    float acc[8][8];
#pragma unroll
    for (int u = 0; u < 8; u++)
#pragma unroll
        for (int v = 0; v < 8; v++) acc[u][v] = 0.f;

    for (int k0 = 0; k0 < KK2; k0 += BK) {
        // A tile: BM x BK, transposed into As[k][m]
#pragma unroll
        for (int l = tid; l < BM * BK; l += 256) {
            int m = l >> 3, kk = l & 7;
            int gr = rowBase + m;
            As[kk][m] = (gr < M) ? A[(size_t)gr * KK2 + k0 + kk] : 0.f;
        }
        // B tile: BK x BN
#pragma unroll
        for (int l = tid; l < BK * BN; l += 256) {
            int kk = l >> 7, nn = l & 127;
            Bs[kk][nn] = B[(size_t)(k0 + kk) * DD + colBase + nn];
        }
        __syncthreads();
#pragma unroll
        for (int kk = 0; kk < BK; kk++) {
            float4 av0 = *(const float4*)&As[kk][tr * 8];
            float4 av1 = *(const float4*)&As[kk][tr * 8 + 4];
            float4 bv0 = *(const float4*)&Bs[kk][tc * 8];
            float4 bv1 = *(const float4*)&Bs[kk][tc * 8 + 4];
            float a[8] = {av0.x, av0.y, av0.z, av0.w, av1.x, av1.y, av1.z, av1.w};
            float b[8] = {bv0.x, bv0.y, bv0.z, bv0.w, bv1.x, bv1.y, bv1.z, bv1.w};
#pragma unroll
            for (int u = 0; u < 8; u++)
#pragma unroll
                for (int v = 0; v < 8; v++) acc[u][v] += a[u] * b[v];
        }
        __syncthreads();
    }
#pragma unroll
    for (int u = 0; u < 8; u++) {
        int gr = rowBase + tr * 8 + u;
        if (gr < M) {
#pragma unroll
            for (int v = 0; v < 8; v++)
                g_h0[(size_t)gr * DD + colBase + tc * 8 + v] = acc[u][v];
        }
    }
}

// ---------------- aggregation 1 + bias + tanh ---------------------------------
// one block (256 threads) per node: thread t owns feature t; coalesced 1KB
// reads of each neighbor row; single write of the result.
__global__ __launch_bounds__(DD) void k_agg1(const float* __restrict__ b1, int n) {
    int i = blockIdx.x;
    int t = threadIdx.x;
    int s = g_rowptr[i], e = g_rowptr[i + 1];
    float acc = 0.f;
    for (int k = s; k < e; k++) {
        int   j  = g_src[k];
        float wt = g_w[k];
        acc += wt * g_h0[(size_t)j * DD + t];
    }
    g_h1[(size_t)i * DD + t] = tanhf(acc + b1[t]);
}

// ---------------- y0 = h1 @ W2 (per-node dot, warp per node) ------------------
__global__ void k_y0(const float* __restrict__ W2, int n) {
    int gw   = (blockIdx.x * blockDim.x + threadIdx.x) >> 5;
    int lane = threadIdx.x & 31;
    if (gw >= n) return;
    float acc = 0.f;
#pragma unroll
    for (int u = 0; u < DD / 32; u++) {
        int c = u * 32 + lane;
        acc += g_h1[(size_t)gw * DD + c] * W2[c];
    }
#pragma unroll
    for (int o = 16; o; o >>= 1) acc += __shfl_xor_sync(0xffffffffu, acc, o);
    if (lane == 0) g_y0[gw] = acc;
}

// ---------------- aggregation 2 + bias + squared-norm reduction ---------------
__global__ void k_agg2norm(const float* __restrict__ b2, int n) {
    __shared__ float sh[8];
    int wib  = threadIdx.x >> 5;
    int lane = threadIdx.x & 31;
    int i    = blockIdx.x * 8 + wib;
    float contrib = 0.f;
    if (i < n) {
        int s = g_rowptr[i], e = g_rowptr[i + 1];
        float acc = 0.f;
        for (int k = s + lane; k < e; k += 32) acc += g_w[k] * g_y0[g_src[k]];
#pragma unroll
        for (int o = 16; o; o >>= 1) acc += __shfl_xor_sync(0xffffffffu, acc, o);
        float z = acc + b2[0];
        contrib = z * z;
    }
    if (lane == 0) sh[wib] = contrib;
    __syncthreads();
    if (threadIdx.x == 0) {
        float s2 = 0.f;
#pragma unroll
        for (int u = 0; u < 8; u++) s2 += sh[u];
        atomicAdd(&g_norm, s2);
    }
}

__global__ void k_final(float* out) { out[0] = sqrtf(g_norm); }

// ---------------- launch ------------------------------------------------------
extern "C" void kernel_launch(void* const* d_in, const int* in_sizes, int n_in,
                              void* d_out, int out_size) {
    const float* x  = (const float*)d_in[0];
    const int*   ei = (const int*)d_in[1];
    const float* W1 = (const float*)d_in[2];
    const float* b1 = (const float*)d_in[3];
    const float* W2 = (const float*)d_in[4];
    const float* b2 = (const float*)d_in[5];
    float* out = (float*)d_out;

    int n = in_sizes[0] / (2 * DD);   // nodes
    int e = in_sizes[1] / 2;          // edges
    const int* row = ei;
    const int* col = ei + e;

    int nb = (n + 1023) / 1024;

    k_init <<<(n + 255) / 256, 256>>>(n);
    k_count<<<(e + 255) / 256, 256>>>(col, e);
    k_dinv <<<(n + 255) / 256, 256>>>(n);
    k_scan1<<<nb, 1024>>>(n);
    k_scan2<<<1, 32>>>(nb);
    k_scan3<<<(n + 255) / 256, 256>>>(n);
    k_cur  <<<(n + 255) / 256, 256>>>(n);
    k_fill <<<(e + 255) / 256, 256>>>(row, col, e);

    dim3 ggrid(DD / BN, (n + BM - 1) / BM);
    k_gemm1<<<ggrid, 256>>>(x, W1, n);

    k_agg1<<<n, DD>>>(b1, n);
    k_y0<<<(n * 32 + 255) / 256, 256>>>(W2, n);
    k_agg2norm<<<(n + 7) / 8, 256>>>(b2, n);
    k_final<<<1, 1>>>(out);
}

// round 3
// speedup vs baseline: 1.2991x; 1.2991x over previous
#include <cuda_runtime.h>
#include <cuda_fp16.h>
#include <math.h>
#include <stdint.h>

#define MAXN 100000
#define MAXE 3200000
#define DD   256          // size_in (output dim of layer 1)
#define DH   128          // DD in half2 units
#define KK2  512          // 2*D (input dim of layer 1)

// ---------------- scratch (device globals) ------------------------------------
__device__ __half2 g_h0h[(size_t)MAXN * DH];   // x @ W1   (fp16 storage)
__device__ __half2 g_h1h[(size_t)MAXN * DH];   // tanh(agg(h0)+b1)
__device__ float g_y0[MAXN];                   // h1 @ W2
__device__ int   g_deg[MAXN];
__device__ float g_dinv[MAXN];
__device__ int   g_rowptr[MAXN + 1];
__device__ int   g_cur[MAXN];
__device__ int   g_src[MAXE + MAXN];
__device__ float g_w[MAXE + MAXN];
__device__ int   g_blksum[256];
__device__ float g_norm;

// ---------------- setup kernels ----------------------------------------------
__global__ void k_init(int n) {
    int i = blockIdx.x * blockDim.x + threadIdx.x;
    if (i < n) g_deg[i] = 1;
    if (i == 0) g_norm = 0.f;
}

__global__ void k_count(const int* __restrict__ col, int e) {
    int i = blockIdx.x * blockDim.x + threadIdx.x;
    if (i < e) atomicAdd(&g_deg[col[i]], 1);
}

__global__ void k_dinv(int n) {
    int i = blockIdx.x * blockDim.x + threadIdx.x;
    if (i < n) g_dinv[i] = rsqrtf((float)g_deg[i]);
}

__global__ void k_scan1(int n) {
    __shared__ int sh[1024];
    int i = blockIdx.x * 1024 + threadIdx.x;
    int v = (i < n) ? g_deg[i] : 0;
    sh[threadIdx.x] = v;
    __syncthreads();
    for (int off = 1; off < 1024; off <<= 1) {
        int t = (threadIdx.x >= off) ? sh[threadIdx.x - off] : 0;
        __syncthreads();
        sh[threadIdx.x] += t;
        __syncthreads();
    }
    if (i < n) g_rowptr[i + 1] = sh[threadIdx.x];
    if (threadIdx.x == 1023) g_blksum[blockIdx.x] = sh[1023];
}

__global__ void k_scan2(int nb) {
    if (threadIdx.x == 0 && blockIdx.x == 0) {
        int run = 0;
        for (int b = 0; b < nb; b++) { int t = g_blksum[b]; g_blksum[b] = run; run += t; }
    }
}

__global__ void k_scan3(int n) {
    int i = blockIdx.x * blockDim.x + threadIdx.x;
    if (i < n) g_rowptr[i + 1] += g_blksum[i >> 10];
    if (i == 0) g_rowptr[0] = 0;
}

__global__ void k_cur(int n) {
    int i = blockIdx.x * blockDim.x + threadIdx.x;
    if (i < n) {
        int p = g_rowptr[i];
        float di = g_dinv[i];
        g_src[p] = i;
        g_w[p]   = di * di;
        g_cur[i] = p + 1;
    }
}

__global__ void k_fill(const int* __restrict__ row, const int* __restrict__ col, int e) {
    int i = blockIdx.x * blockDim.x + threadIdx.x;
    if (i < e) {
        int r = row[i], c = col[i];
        int p = atomicAdd(&g_cur[c], 1);
        g_src[p] = r;
        g_w[p]   = g_dinv[r] * g_dinv[c];
    }
}

// ---------------- GEMM1: h0 = x @ W1, double-buffered, fp16 output -----------
#define BM 128
#define BN 128
#define BK 16
__global__ __launch_bounds__(256, 2) void k_gemm1(const float* __restrict__ A,
                                                  const float* __restrict__ B, int M) {
    __shared__ float As[2][BK][BM + 4];
    __shared__ float Bs[2][BK][BN + 4];
    int tid = threadIdx.x;
    int tr = tid >> 4;            // 0..15
    int tc = tid & 15;            // 0..15
    int rowBase = blockIdx.y * BM;
    int colBase = blockIdx.x * BN;

    // A loader: 512 float4 slots over 128 rows x 4 kgroups
    int am = tid & 127;
    int ak = (tid >> 7) * 4;      // 0 or 4; second slot adds +8
    // B loader: 512 float4 slots over 16 krows x 32 colgroups
    int bk = tid >> 5;            // 0..7; second slot adds +8
    int bn = (tid & 31) * 4;

    float acc[8][8];
#pragma unroll
    for (int u = 0; u < 8; u++)
#pragma unroll
        for (int v = 0; v < 8; v++) acc[u][v] = 0.f;

    int grA = rowBase + am;
    bool okA = (grA < M);
    const float4* Arow = (const float4*)&A[(size_t)(okA ? grA : 0) * KK2];

    // prologue: load tile 0 into buf 0
    {
        float4 z = make_float4(0.f, 0.f, 0.f, 0.f);
        float4 a0 = okA ? Arow[(0 + ak) >> 2] : z;
        float4 a1 = okA ? Arow[(0 + ak + 8) >> 2] : z;
        As[0][ak + 0][am] = a0.x; As[0][ak + 1][am] = a0.y;
        As[0][ak + 2][am] = a0.z; As[0][ak + 3][am] = a0.w;
        As[0][ak + 8][am] = a1.x; As[0][ak + 9][am] = a1.y;
        As[0][ak + 10][am] = a1.z; As[0][ak + 11][am] = a1.w;
        *(float4*)&Bs[0][bk][bn]     = *(const float4*)&B[(size_t)(bk) * DD + colBase + bn];
        *(float4*)&Bs[0][bk + 8][bn] = *(const float4*)&B[(size_t)(bk + 8) * DD + colBase + bn];
    }
    __syncthreads();

    for (int k0 = 0; k0 < KK2; k0 += BK) {
        int buf = (k0 >> 4) & 1;
        if (k0 + BK < KK2) {
            int nk = k0 + BK;
            float4 z = make_float4(0.f, 0.f, 0.f, 0.f);
            float4 a0 = okA ? Arow[(nk + ak) >> 2] : z;
            float4 a1 = okA ? Arow[(nk + ak + 8) >> 2] : z;
            int nb = buf ^ 1;
            As[nb][ak + 0][am] = a0.x; As[nb][ak + 1][am] = a0.y;
            As[nb][ak + 2][am] = a0.z; As[nb][ak + 3][am] = a0.w;
            As[nb][ak + 8][am] = a1.x; As[nb][ak + 9][am] = a1.y;
            As[nb][ak + 10][am] = a1.z; As[nb][ak + 11][am] = a1.w;
            *(float4*)&Bs[nb][bk][bn]     = *(const float4*)&B[(size_t)(nk + bk) * DD + colBase + bn];
            *(float4*)&Bs[nb][bk + 8][bn] = *(const float4*)&B[(size_t)(nk + bk + 8) * DD + colBase + bn];
        }
#pragma unroll
        for (int kk = 0; kk < BK; kk++) {
            float4 av0 = *(const float4*)&As[buf][kk][tr * 8];
            float4 av1 = *(const float4*)&As[buf][kk][tr * 8 + 4];
            float4 bv0 = *(const float4*)&Bs[buf][kk][tc * 8];
            float4 bv1 = *(const float4*)&Bs[buf][kk][tc * 8 + 4];
            float a[8] = {av0.x, av0.y, av0.z, av0.w, av1.x, av1.y, av1.z, av1.w};
            float b[8] = {bv0.x, bv0.y, bv0.z, bv0.w, bv1.x, bv1.y, bv1.z, bv1.w};
#pragma unroll
            for (int u = 0; u < 8; u++)
#pragma unroll
                for (int v = 0; v < 8; v++) acc[u][v] += a[u] * b[v];
        }
        __syncthreads();
    }

    // epilogue: convert to fp16, 16B stores
#pragma unroll
    for (int u = 0; u < 8; u++) {
        int gr = rowBase + tr * 8 + u;
        if (gr < M) {
            uint4 pk;
            __half2* hp = reinterpret_cast<__half2*>(&pk);
#pragma unroll
            for (int v = 0; v < 4; v++)
                hp[v] = __floats2half2_rn(acc[u][2 * v], acc[u][2 * v + 1]);
            *(uint4*)&g_h0h[(size_t)gr * DH + (colBase >> 1) + tc * 4] = pk;
        }
    }
}

// ---------------- aggregation 1 + bias + tanh (fp16 rows) ---------------------
__global__ __launch_bounds__(DH) void k_agg1(const float* __restrict__ b1, int n) {
    int i = blockIdx.x;
    int t = threadIdx.x;              // half2 feature pair
    int s = g_rowptr[i], e = g_rowptr[i + 1];
    float ax = 0.f, ay = 0.f;
    for (int k = s; k < e; k++) {
        int   j  = g_src[k];
        float wt = g_w[k];
        float2 f = __half22float2(g_h0h[(size_t)j * DH + t]);
        ax += wt * f.x;
        ay += wt * f.y;
    }
    float2 bb = ((const float2*)b1)[t];
    g_h1h[(size_t)i * DH + t] = __floats2half2_rn(tanhf(ax + bb.x), tanhf(ay + bb.y));
}

// ---------------- y0 = h1 @ W2 (warp per node) --------------------------------
__global__ void k_y0(const float* __restrict__ W2, int n) {
    int gw   = (blockIdx.x * blockDim.x + threadIdx.x) >> 5;
    int lane = threadIdx.x & 31;
    if (gw >= n) return;
    float acc = 0.f;
#pragma unroll
    for (int u = 0; u < DH / 32; u++) {
        int c = u * 32 + lane;
        float2 f  = __half22float2(g_h1h[(size_t)gw * DH + c]);
        float2 w2 = ((const float2*)W2)[c];
        acc += f.x * w2.x + f.y * w2.y;
    }
#pragma unroll
    for (int o = 16; o; o >>= 1) acc += __shfl_xor_sync(0xffffffffu, acc, o);
    if (lane == 0) g_y0[gw] = acc;
}

// ---------------- aggregation 2 + bias + squared-norm reduction ---------------
__global__ void k_agg2norm(const float* __restrict__ b2, int n) {
    __shared__ float sh[8];
    int wib  = threadIdx.x >> 5;
    int lane = threadIdx.x & 31;
    int i    = blockIdx.x * 8 + wib;
    float contrib = 0.f;
    if (i < n) {
        int s = g_rowptr[i], e = g_rowptr[i + 1];
        float acc = 0.f;
        for (int k = s + lane; k < e; k += 32) acc += g_w[k] * g_y0[g_src[k]];
#pragma unroll
        for (int o = 16; o; o >>= 1) acc += __shfl_xor_sync(0xffffffffu, acc, o);
        float z = acc + b2[0];
        contrib = z * z;
    }
    if (lane == 0) sh[wib] = contrib;
    __syncthreads();
    if (threadIdx.x == 0) {
        float s2 = 0.f;
#pragma unroll
        for (int u = 0; u < 8; u++) s2 += sh[u];
        atomicAdd(&g_norm, s2);
    }
}

__global__ void k_final(float* out) { out[0] = sqrtf(g_norm); }

// ---------------- launch ------------------------------------------------------
extern "C" void kernel_launch(void* const* d_in, const int* in_sizes, int n_in,
                              void* d_out, int out_size) {
    const float* x  = (const float*)d_in[0];
    const int*   ei = (const int*)d_in[1];
    const float* W1 = (const float*)d_in[2];
    const float* b1 = (const float*)d_in[3];
    const float* W2 = (const float*)d_in[4];
    const float* b2 = (const float*)d_in[5];
    float* out = (float*)d_out;

    int n = in_sizes[0] / (2 * DD);
    int e = in_sizes[1] / 2;
    const int* row = ei;
    const int* col = ei + e;

    int nb = (n + 1023) / 1024;

    k_init <<<(n + 255) / 256, 256>>>(n);
    k_count<<<(e + 255) / 256, 256>>>(col, e);
    k_dinv <<<(n + 255) / 256, 256>>>(n);
    k_scan1<<<nb, 1024>>>(n);
    k_scan2<<<1, 32>>>(nb);
    k_scan3<<<(n + 255) / 256, 256>>>(n);
    k_cur  <<<(n + 255) / 256, 256>>>(n);
    k_fill <<<(e + 255) / 256, 256>>>(row, col, e);

    dim3 ggrid(DD / BN, (n + BM - 1) / BM);
    k_gemm1<<<ggrid, 256>>>(x, W1, n);

    k_agg1<<<n, DH>>>(b1, n);
    k_y0<<<(n * 32 + 255) / 256, 256>>>(W2, n);
    k_agg2norm<<<(n + 7) / 8, 256>>>(b2, n);
    k_final<<<1, 1>>>(out);
}

// round 4
// speedup vs baseline: 3.0239x; 2.3276x over previous
#include <cuda_runtime.h>
#include <cuda_fp16.h>
#include <cuda_bf16.h>
#include <math.h>
#include <stdint.h>

#define MAXN 100000
#define MAXE 3200000
#define DD   256          // size_in (output dim of layer 1)
#define DH   128          // DD in half2 units
#define KK2  512          // 2*D (input dim of layer 1)

// ---------------- scratch (device globals) ------------------------------------
__device__ __half2 g_h0h[(size_t)MAXN * DH];   // x @ W1   (fp16 storage)
__device__ float g_y0[MAXN];                   // per-node scalar after layer1+W2
__device__ int   g_deg[MAXN];
__device__ float g_dinv[MAXN];
__device__ int   g_rowptr[MAXN + 1];
__device__ int   g_cur[MAXN];
__device__ int   g_src[MAXE + MAXN];
__device__ float g_w[MAXE + MAXN];
__device__ int   g_blksum[256];
__device__ float g_norm;

// ---------------- setup kernels ----------------------------------------------
__global__ void k_init(int n) {
    int i = blockIdx.x * blockDim.x + threadIdx.x;
    if (i < n) g_deg[i] = 1;
    if (i == 0) g_norm = 0.f;
}

__global__ void k_count(const int* __restrict__ col, int e) {
    int i = blockIdx.x * blockDim.x + threadIdx.x;
    if (i < e) atomicAdd(&g_deg[col[i]], 1);
}

__global__ void k_dinv(int n) {
    int i = blockIdx.x * blockDim.x + threadIdx.x;
    if (i < n) g_dinv[i] = rsqrtf((float)g_deg[i]);
}

__global__ void k_scan1(int n) {
    __shared__ int sh[1024];
    int i = blockIdx.x * 1024 + threadIdx.x;
    int v = (i < n) ? g_deg[i] : 0;
    sh[threadIdx.x] = v;
    __syncthreads();
    for (int off = 1; off < 1024; off <<= 1) {
        int t = (threadIdx.x >= off) ? sh[threadIdx.x - off] : 0;
        __syncthreads();
        sh[threadIdx.x] += t;
        __syncthreads();
    }
    if (i < n) g_rowptr[i + 1] = sh[threadIdx.x];
    if (threadIdx.x == 1023) g_blksum[blockIdx.x] = sh[1023];
}

__global__ void k_scan2(int nb) {
    if (threadIdx.x == 0 && blockIdx.x == 0) {
        int run = 0;
        for (int b = 0; b < nb; b++) { int t = g_blksum[b]; g_blksum[b] = run; run += t; }
    }
}

__global__ void k_scan3(int n) {
    int i = blockIdx.x * blockDim.x + threadIdx.x;
    if (i < n) g_rowptr[i + 1] += g_blksum[i >> 10];
    if (i == 0) g_rowptr[0] = 0;
}

__global__ void k_cur(int n) {
    int i = blockIdx.x * blockDim.x + threadIdx.x;
    if (i < n) {
        int p = g_rowptr[i];
        float di = g_dinv[i];
        g_src[p] = i;
        g_w[p]   = di * di;
        g_cur[i] = p + 1;
    }
}

__global__ void k_fill(const int* __restrict__ row, const int* __restrict__ col, int e) {
    int i = blockIdx.x * blockDim.x + threadIdx.x;
    if (i < e) {
        int r = row[i], c = col[i];
        int p = atomicAdd(&g_cur[c], 1);
        g_src[p] = r;
        g_w[p]   = g_dinv[r] * g_dinv[c];
    }
}

// ---------------- GEMM1 (tensor core, bf16 mma, fp32 accum) -------------------
// h0 = x[M,512] @ W1[512,256]; output fp16 to g_h0h.
#define BM 128
#define BN 128
#define BK 32

__device__ __forceinline__ uint32_t smem_u32(const void* p) {
    return (uint32_t)__cvta_generic_to_shared(p);
}

__device__ __forceinline__ void ldm_x4(uint32_t& r0, uint32_t& r1, uint32_t& r2, uint32_t& r3,
                                       uint32_t addr) {
    asm volatile("ldmatrix.sync.aligned.m8n8.x4.shared.b16 {%0,%1,%2,%3}, [%4];"
                 : "=r"(r0), "=r"(r1), "=r"(r2), "=r"(r3) : "r"(addr));
}
__device__ __forceinline__ void ldm_x4_t(uint32_t& r0, uint32_t& r1, uint32_t& r2, uint32_t& r3,
                                         uint32_t addr) {
    asm volatile("ldmatrix.sync.aligned.m8n8.x4.trans.shared.b16 {%0,%1,%2,%3}, [%4];"
                 : "=r"(r0), "=r"(r1), "=r"(r2), "=r"(r3) : "r"(addr));
}
__device__ __forceinline__ void mma16816(float* c, const uint32_t* a, uint32_t b0, uint32_t b1) {
    asm volatile("mma.sync.aligned.m16n8k16.row.col.f32.bf16.bf16.f32 "
                 "{%0,%1,%2,%3}, {%4,%5,%6,%7}, {%8,%9}, {%0,%1,%2,%3};"
                 : "+f"(c[0]), "+f"(c[1]), "+f"(c[2]), "+f"(c[3])
                 : "r"(a[0]), "r"(a[1]), "r"(a[2]), "r"(a[3]), "r"(b0), "r"(b1));
}

__global__ __launch_bounds__(256, 1) void k_gemm1(const float* __restrict__ A,
                                                  const float* __restrict__ B, int M) {
    __shared__ __nv_bfloat16 As[2][BM][BK + 8];   // padded: stride 40 bf16 = 80B
    __shared__ __nv_bfloat16 Bs[2][BK][BN + 8];   // padded: stride 136 bf16 = 272B

    int tid  = threadIdx.x;
    int wid  = tid >> 5, lane = tid & 31;
    int wm   = wid & 3;           // warp row (32 rows each)
    int wn   = wid >> 2;          // warp col (64 cols each)
    int rowBase = blockIdx.y * BM;
    int colBase = blockIdx.x * BN;

    // A loader mapping: 2 threads per row, 16 floats each
    int arow = tid >> 1;
    int acol = (tid & 1) * 16;
    int grA  = rowBase + arow;
    bool okA = (grA < M);
    const float4* A4 = (const float4*)A;
    size_t aBase = (size_t)(okA ? grA : 0) * (KK2 / 4);

    // B loader mapping: 8 threads per k-row, 4 float4 each (stride 8 f4)
    int bkr = tid >> 3;
    int bf4 = tid & 7;
    const float4* B4 = (const float4*)B;

    float acc[2][8][4];
#pragma unroll
    for (int mi = 0; mi < 2; mi++)
#pragma unroll
        for (int ni = 0; ni < 8; ni++)
#pragma unroll
            for (int q = 0; q < 4; q++) acc[mi][ni][q] = 0.f;

    float4 ra[4], rb[4];

    auto loadG = [&](int k0) {
        float4 z = make_float4(0.f, 0.f, 0.f, 0.f);
#pragma unroll
        for (int j = 0; j < 4; j++)
            ra[j] = okA ? A4[aBase + ((k0 + acol) >> 2) + j] : z;
#pragma unroll
        for (int j = 0; j < 4; j++)
            rb[j] = B4[(size_t)(k0 + bkr) * (DD / 4) + (colBase >> 2) + bf4 + j * 8];
    };
    auto storeS = [&](int buf) {
        __nv_bfloat162 pa[8];
#pragma unroll
        for (int j = 0; j < 4; j++) {
            pa[2 * j]     = __float22bfloat162_rn(make_float2(ra[j].x, ra[j].y));
            pa[2 * j + 1] = __float22bfloat162_rn(make_float2(ra[j].z, ra[j].w));
        }
        *(uint4*)&As[buf][arow][acol]     = ((uint4*)pa)[0];
        *(uint4*)&As[buf][arow][acol + 8] = ((uint4*)pa)[1];
#pragma unroll
        for (int j = 0; j < 4; j++) {
            __nv_bfloat162 pb[2];
            pb[0] = __float22bfloat162_rn(make_float2(rb[j].x, rb[j].y));
            pb[1] = __float22bfloat162_rn(make_float2(rb[j].z, rb[j].w));
            *(uint2*)&Bs[buf][bkr][(bf4 + j * 8) * 4] = *(uint2*)pb;
        }
    };

    loadG(0);
    storeS(0);
    __syncthreads();

    const int NT = KK2 / BK;   // 16 tiles
    for (int t = 0; t < NT; t++) {
        int buf = t & 1;
        if (t + 1 < NT) loadG((t + 1) * BK);

        // compute current tile: 2 k16 steps
#pragma unroll
        for (int ks = 0; ks < 2; ks++) {
            uint32_t afr[2][4];
#pragma unroll
            for (int mi = 0; mi < 2; mi++) {
                uint32_t ad = smem_u32(&As[buf][wm * 32 + mi * 16 + (lane & 15)]
                                          [ks * 16 + (lane >> 4) * 8]);
                ldm_x4(afr[mi][0], afr[mi][1], afr[mi][2], afr[mi][3], ad);
            }
#pragma unroll
            for (int p = 0; p < 4; p++) {
                uint32_t b0, b1, b2, b3;
                uint32_t bd = smem_u32(&Bs[buf][ks * 16 + (lane & 15)]
                                          [wn * 64 + p * 16 + (lane >> 4) * 8]);
                ldm_x4_t(b0, b1, b2, b3, bd);
                mma16816(acc[0][2 * p],     afr[0], b0, b1);
                mma16816(acc[1][2 * p],     afr[1], b0, b1);
                mma16816(acc[0][2 * p + 1], afr[0], b2, b3);
                mma16816(acc[1][2 * p + 1], afr[1], b2, b3);
            }
        }
        __syncthreads();
        if (t + 1 < NT) {
            storeS(buf ^ 1);
            __syncthreads();
        }
    }

    // epilogue: fragments -> fp16 global
#pragma unroll
    for (int mi = 0; mi < 2; mi++) {
#pragma unroll
        for (int ni = 0; ni < 8; ni++) {
            int r0 = rowBase + wm * 32 + mi * 16 + (lane >> 2);
            int c  = colBase + wn * 64 + ni * 8 + (lane & 3) * 2;
            if (r0 < M)
                g_h0h[(size_t)r0 * DH + (c >> 1)] =
                    __floats2half2_rn(acc[mi][ni][0], acc[mi][ni][1]);
            int r1 = r0 + 8;
            if (r1 < M)
                g_h0h[(size_t)r1 * DH + (c >> 1)] =
                    __floats2half2_rn(acc[mi][ni][2], acc[mi][ni][3]);
        }
    }
}

// ---------------- fused aggregation1 + bias + tanh + W2 dot -------------------
// warp per node: lane owns 8 features (one uint4 = 4 half2). 4-way neighbor
// unroll for MLP. Result: g_y0[i] = (tanh(agg(h0)[i] + b1)) . W2
__device__ __forceinline__ void acc_row(float* a8, uint4 v, float wt) {
    __half2* h = (__half2*)&v;
#pragma unroll
    for (int q = 0; q < 4; q++) {
        float2 f = __half22float2(h[q]);
        a8[2 * q]     += wt * f.x;
        a8[2 * q + 1] += wt * f.y;
    }
}

__global__ __launch_bounds__(256) void k_agg1y(const float* __restrict__ b1,
                                               const float* __restrict__ W2, int n) {
    int gw   = (blockIdx.x * blockDim.x + threadIdx.x) >> 5;
    int lane = threadIdx.x & 31;
    if (gw >= n) return;
    int s = g_rowptr[gw], e = g_rowptr[gw + 1];

    const uint4* base = (const uint4*)g_h0h;   // 32 uint4 per node row

    float a8[8];
#pragma unroll
    for (int q = 0; q < 8; q++) a8[q] = 0.f;

    int k = s;
    for (; k + 4 <= e; k += 4) {
        int   j0 = g_src[k],     j1 = g_src[k + 1];
        int   j2 = g_src[k + 2], j3 = g_src[k + 3];
        float w0 = g_w[k],       w1 = g_w[k + 1];
        float w2 = g_w[k + 2],   w3 = g_w[k + 3];
        uint4 v0 = base[(size_t)j0 * 32 + lane];
        uint4 v1 = base[(size_t)j1 * 32 + lane];
        uint4 v2 = base[(size_t)j2 * 32 + lane];
        uint4 v3 = base[(size_t)j3 * 32 + lane];
        acc_row(a8, v0, w0);
        acc_row(a8, v1, w1);
        acc_row(a8, v2, w2);
        acc_row(a8, v3, w3);
    }
    for (; k < e; k++) {
        uint4 v = base[(size_t)g_src[k] * 32 + lane];
        acc_row(a8, v, g_w[k]);
    }

    // bias + tanh + dot with W2 (lane's 8 features)
    float4 b1a = ((const float4*)b1)[lane * 2];
    float4 b1b = ((const float4*)b1)[lane * 2 + 1];
    float4 w2a = ((const float4*)W2)[lane * 2];
    float4 w2b = ((const float4*)W2)[lane * 2 + 1];
    float dot = 0.f;
    dot += tanhf(a8[0] + b1a.x) * w2a.x;
    dot += tanhf(a8[1] + b1a.y) * w2a.y;
    dot += tanhf(a8[2] + b1a.z) * w2a.z;
    dot += tanhf(a8[3] + b1a.w) * w2a.w;
    dot += tanhf(a8[4] + b1b.x) * w2b.x;
    dot += tanhf(a8[5] + b1b.y) * w2b.y;
    dot += tanhf(a8[6] + b1b.z) * w2b.z;
    dot += tanhf(a8[7] + b1b.w) * w2b.w;
#pragma unroll
    for (int o = 16; o; o >>= 1) dot += __shfl_xor_sync(0xffffffffu, dot, o);
    if (lane == 0) g_y0[gw] = dot;
}

// ---------------- aggregation 2 + bias + squared-norm reduction ---------------
__global__ void k_agg2norm(const float* __restrict__ b2, int n) {
    __shared__ float sh[8];
    int wib  = threadIdx.x >> 5;
    int lane = threadIdx.x & 31;
    int i    = blockIdx.x * 8 + wib;
    float contrib = 0.f;
    if (i < n) {
        int s = g_rowptr[i], e = g_rowptr[i + 1];
        float acc = 0.f;
        for (int k = s + lane; k < e; k += 32) acc += g_w[k] * g_y0[g_src[k]];
#pragma unroll
        for (int o = 16; o; o >>= 1) acc += __shfl_xor_sync(0xffffffffu, acc, o);
        float z = acc + b2[0];
        contrib = z * z;
    }
    if (lane == 0) sh[wib] = contrib;
    __syncthreads();
    if (threadIdx.x == 0) {
        float s2 = 0.f;
#pragma unroll
        for (int u = 0; u < 8; u++) s2 += sh[u];
        atomicAdd(&g_norm, s2);
    }
}

__global__ void k_final(float* out) { out[0] = sqrtf(g_norm); }

// ---------------- launch ------------------------------------------------------
extern "C" void kernel_launch(void* const* d_in, const int* in_sizes, int n_in,
                              void* d_out, int out_size) {
    const float* x  = (const float*)d_in[0];
    const int*   ei = (const int*)d_in[1];
    const float* W1 = (const float*)d_in[2];
    const float* b1 = (const float*)d_in[3];
    const float* W2 = (const float*)d_in[4];
    const float* b2 = (const float*)d_in[5];
    float* out = (float*)d_out;

    int n = in_sizes[0] / (2 * DD);
    int e = in_sizes[1] / 2;
    const int* row = ei;
    const int* col = ei + e;

    int nb = (n + 1023) / 1024;

    k_init <<<(n + 255) / 256, 256>>>(n);
    k_count<<<(e + 255) / 256, 256>>>(col, e);
    k_dinv <<<(n + 255) / 256, 256>>>(n);
    k_scan1<<<nb, 1024>>>(n);
    k_scan2<<<1, 32>>>(nb);
    k_scan3<<<(n + 255) / 256, 256>>>(n);
    k_cur  <<<(n + 255) / 256, 256>>>(n);
    k_fill <<<(e + 255) / 256, 256>>>(row, col, e);

    dim3 ggrid(DD / BN, (n + BM - 1) / BM);
    k_gemm1<<<ggrid, 256>>>(x, W1, n);

    k_agg1y<<<(n + 7) / 8, 256>>>(b1, W2, n);
    k_agg2norm<<<(n + 7) / 8, 256>>>(b2, n);
    k_final<<<1, 1>>>(out);
}

// round 7
// speedup vs baseline: 3.2014x; 1.0587x over previous
#include <cuda_runtime.h>
#include <cuda_fp16.h>
#include <cuda_bf16.h>
#include <math.h>
#include <stdint.h>

#define MAXN 100000
#define MAXE 3200000
#define DD   256          // size_in (output dim of layer 1)
#define DH   128          // DD in half2 units
#define KK2  512          // 2*D (input dim of layer 1)

// ---------------- scratch (device globals) ------------------------------------
__device__ __half2 g_h0h[(size_t)MAXN * DH];   // x @ W1   (fp16 storage)
__device__ float g_y0[MAXN];                   // per-node scalar after layer1+W2
__device__ int   g_deg[MAXN];                  // edge-only degree (self loop implicit)
__device__ float g_dinv[MAXN];
__device__ int   g_rowptr[MAXN + 1];
__device__ int   g_cur[MAXN];
__device__ int2  g_adj[MAXE + MAXN];           // (src, weight-bits) interleaved
__device__ int   g_blksum[256];
__device__ float g_norm;

// ---------------- setup kernels ----------------------------------------------
__global__ void k_init(int n) {
    int i = blockIdx.x * blockDim.x + threadIdx.x;
    if (i < n) g_deg[i] = 0;
}

__global__ void k_count(const int* __restrict__ col, int e) {
    int i = blockIdx.x * blockDim.x + threadIdx.x;
    if (i < e) atomicAdd(&g_deg[col[i]], 1);
}

// scan of (deg+1); also computes dinv
__global__ void k_scan1(int n) {
    __shared__ int sh[1024];
    int i = blockIdx.x * 1024 + threadIdx.x;
    int d = (i < n) ? g_deg[i] : -1;
    int v = d + 1;                      // self loop included
    if (i < n) g_dinv[i] = rsqrtf((float)v);
    sh[threadIdx.x] = v;
    __syncthreads();
    for (int off = 1; off < 1024; off <<= 1) {
        int t = (threadIdx.x >= off) ? sh[threadIdx.x - off] : 0;
        __syncthreads();
        sh[threadIdx.x] += t;
        __syncthreads();
    }
    if (i < n) g_rowptr[i + 1] = sh[threadIdx.x];
    if (threadIdx.x == 1023) g_blksum[blockIdx.x] = sh[1023];
}

__global__ void k_scan2(int nb) {
    if (threadIdx.x == 0 && blockIdx.x == 0) {
        int run = 0;
        for (int b = 0; b < nb; b++) { int t = g_blksum[b]; g_blksum[b] = run; run += t; }
        g_norm = 0.f;
    }
}

// finalize rowptr, write self-loop entry, init cursor
__global__ void k_scan3(int n) {
    int i = blockIdx.x * blockDim.x + threadIdx.x;
    if (i < n) {
        int rp1 = g_rowptr[i + 1] + g_blksum[i >> 10];
        g_rowptr[i + 1] = rp1;
        int cnt = g_deg[i] + 1;
        int p = rp1 - cnt;              // == rowptr[i]
        float di = g_dinv[i];
        g_adj[p] = make_int2(i, __float_as_int(di * di));
        g_cur[i] = p + 1;
    }
    if (i == 0) g_rowptr[0] = 0;
}

__global__ void k_fill(const int* __restrict__ row, const int* __restrict__ col, int e) {
    int i = blockIdx.x * blockDim.x + threadIdx.x;
    if (i < e) {
        int r = row[i], c = col[i];
        int p = atomicAdd(&g_cur[c], 1);
        g_adj[p] = make_int2(r, __float_as_int(g_dinv[r] * g_dinv[c]));
    }
}

// ---------------- GEMM1 (tensor core, bf16 mma, fp32 accum) -------------------
#define BM 128
#define BN 128
#define BK 32

__device__ __forceinline__ uint32_t smem_u32(const void* p) {
    return (uint32_t)__cvta_generic_to_shared(p);
}

__device__ __forceinline__ void ldm_x4(uint32_t& r0, uint32_t& r1, uint32_t& r2, uint32_t& r3,
                                       uint32_t addr) {
    asm volatile("ldmatrix.sync.aligned.m8n8.x4.shared.b16 {%0,%1,%2,%3}, [%4];"
                 : "=r"(r0), "=r"(r1), "=r"(r2), "=r"(r3) : "r"(addr));
}
__device__ __forceinline__ void ldm_x4_t(uint32_t& r0, uint32_t& r1, uint32_t& r2, uint32_t& r3,
                                         uint32_t addr) {
    asm volatile("ldmatrix.sync.aligned.m8n8.x4.trans.shared.b16 {%0,%1,%2,%3}, [%4];"
                 : "=r"(r0), "=r"(r1), "=r"(r2), "=r"(r3) : "r"(addr));
}
__device__ __forceinline__ void mma16816(float* c, const uint32_t* a, uint32_t b0, uint32_t b1) {
    asm volatile("mma.sync.aligned.m16n8k16.row.col.f32.bf16.bf16.f32 "
                 "{%0,%1,%2,%3}, {%4,%5,%6,%7}, {%8,%9}, {%0,%1,%2,%3};"
                 : "+f"(c[0]), "+f"(c[1]), "+f"(c[2]), "+f"(c[3])
                 : "r"(a[0]), "r"(a[1]), "r"(a[2]), "r"(a[3]), "r"(b0), "r"(b1));
}

__global__ __launch_bounds__(256, 1) void k_gemm1(const float* __restrict__ A,
                                                  const float* __restrict__ B, int M) {
    __shared__ __nv_bfloat16 As[2][BM][BK + 8];
    __shared__ __nv_bfloat16 Bs[2][BK][BN + 8];

    int tid  = threadIdx.x;
    int wid  = tid >> 5, lane = tid & 31;
    int wm   = wid & 3;
    int wn   = wid >> 2;
    int rowBase = blockIdx.y * BM;
    int colBase = blockIdx.x * BN;

    int arow = tid >> 1;
    int acol = (tid & 1) * 16;
    int grA  = rowBase + arow;
    bool okA = (grA < M);
    const float4* A4 = (const float4*)A;
    size_t aBase = (size_t)(okA ? grA : 0) * (KK2 / 4);

    int bkr = tid >> 3;
    int bf4 = tid & 7;
    const float4* B4 = (const float4*)B;

    float acc[2][8][4];
#pragma unroll
    for (int mi = 0; mi < 2; mi++)
#pragma unroll
        for (int ni = 0; ni < 8; ni++)
#pragma unroll
            for (int q = 0; q < 4; q++) acc[mi][ni][q] = 0.f;

    float4 ra[4], rb[4];

    auto loadG = [&](int k0) {
        float4 z = make_float4(0.f, 0.f, 0.f, 0.f);
#pragma unroll
        for (int j = 0; j < 4; j++)
            ra[j] = okA ? A4[aBase + ((k0 + acol) >> 2) + j] : z;
#pragma unroll
        for (int j = 0; j < 4; j++)
            rb[j] = B4[(size_t)(k0 + bkr) * (DD / 4) + (colBase >> 2) + bf4 + j * 8];
    };
    auto storeS = [&](int buf) {
        __nv_bfloat162 pa[8];
#pragma unroll
        for (int j = 0; j < 4; j++) {
            pa[2 * j]     = __float22bfloat162_rn(make_float2(ra[j].x, ra[j].y));
            pa[2 * j + 1] = __float22bfloat162_rn(make_float2(ra[j].z, ra[j].w));
        }
        *(uint4*)&As[buf][arow][acol]     = ((uint4*)pa)[0];
        *(uint4*)&As[buf][arow][acol + 8] = ((uint4*)pa)[1];
#pragma unroll
        for (int j = 0; j < 4; j++) {
            __nv_bfloat162 pb[2];
            pb[0] = __float22bfloat162_rn(make_float2(rb[j].x, rb[j].y));
            pb[1] = __float22bfloat162_rn(make_float2(rb[j].z, rb[j].w));
            *(uint2*)&Bs[buf][bkr][(bf4 + j * 8) * 4] = *(uint2*)pb;
        }
    };

    loadG(0);
    storeS(0);
    __syncthreads();

    const int NT = KK2 / BK;
    for (int t = 0; t < NT; t++) {
        int buf = t & 1;
        if (t + 1 < NT) loadG((t + 1) * BK);

#pragma unroll
        for (int ks = 0; ks < 2; ks++) {
            uint32_t afr[2][4];
#pragma unroll
            for (int mi = 0; mi < 2; mi++) {
                uint32_t ad = smem_u32(&As[buf][wm * 32 + mi * 16 + (lane & 15)]
                                          [ks * 16 + (lane >> 4) * 8]);
                ldm_x4(afr[mi][0], afr[mi][1], afr[mi][2], afr[mi][3], ad);
            }
#pragma unroll
            for (int p = 0; p < 4; p++) {
                uint32_t b0, b1, b2, b3;
                uint32_t bd = smem_u32(&Bs[buf][ks * 16 + (lane & 15)]
                                          [wn * 64 + p * 16 + (lane >> 4) * 8]);
                ldm_x4_t(b0, b1, b2, b3, bd);
                mma16816(acc[0][2 * p],     afr[0], b0, b1);
                mma16816(acc[1][2 * p],     afr[1], b0, b1);
                mma16816(acc[0][2 * p + 1], afr[0], b2, b3);
                mma16816(acc[1][2 * p + 1], afr[1], b2, b3);
            }
        }
        __syncthreads();
        if (t + 1 < NT) {
            storeS(buf ^ 1);
            __syncthreads();
        }
    }

#pragma unroll
    for (int mi = 0; mi < 2; mi++) {
#pragma unroll
        for (int ni = 0; ni < 8; ni++) {
            int r0 = rowBase + wm * 32 + mi * 16 + (lane >> 2);
            int c  = colBase + wn * 64 + ni * 8 + (lane & 3) * 2;
            if (r0 < M)
                g_h0h[(size_t)r0 * DH + (c >> 1)] =
                    __floats2half2_rn(acc[mi][ni][0], acc[mi][ni][1]);
            int r1 = r0 + 8;
            if (r1 < M)
                g_h0h[(size_t)r1 * DH + (c >> 1)] =
                    __floats2half2_rn(acc[mi][ni][2], acc[mi][ni][3]);
        }
    }
}

// ---------------- fused aggregation1 + bias + tanh + W2 dot -------------------
__device__ __forceinline__ void acc_row(float* a8, uint4 v, float wt) {
    __half2* h = (__half2*)&v;
#pragma unroll
    for (int q = 0; q < 4; q++) {
        float2 f = __half22float2(h[q]);
        a8[2 * q]     += wt * f.x;
        a8[2 * q + 1] += wt * f.y;
    }
}

__global__ __launch_bounds__(256) void k_agg1y(const float* __restrict__ b1,
                                               const float* __restrict__ W2, int n) {
    int gw   = (blockIdx.x * blockDim.x + threadIdx.x) >> 5;
    int lane = threadIdx.x & 31;
    if (gw >= n) return;
    int s = g_rowptr[gw], e = g_rowptr[gw + 1];

    const uint4* base = (const uint4*)g_h0h;   // 32 uint4 per node row

    float a8[8];
#pragma unroll
    for (int q = 0; q < 8; q++) a8[q] = 0.f;

    int k = s;
#pragma unroll 1
    for (; k + 8 <= e; k += 8) {
        int2 ad[8];
#pragma unroll
        for (int u = 0; u < 8; u++) ad[u] = g_adj[k + u];
        uint4 v[8];
#pragma unroll
        for (int u = 0; u < 8; u++) v[u] = base[(size_t)ad[u].x * 32 + lane];
#pragma unroll
        for (int u = 0; u < 8; u++) acc_row(a8, v[u], __int_as_float(ad[u].y));
    }
    for (; k < e; k++) {
        int2 ad = g_adj[k];
        acc_row(a8, base[(size_t)ad.x * 32 + lane], __int_as_float(ad.y));
    }

    float4 b1a = ((const float4*)b1)[lane * 2];
    float4 b1b = ((const float4*)b1)[lane * 2 + 1];
    float4 w2a = ((const float4*)W2)[lane * 2];
    float4 w2b = ((const float4*)W2)[lane * 2 + 1];
    float dot = 0.f;
    dot += tanhf(a8[0] + b1a.x) * w2a.x;
    dot += tanhf(a8[1] + b1a.y) * w2a.y;
    dot += tanhf(a8[2] + b1a.z) * w2a.z;
    dot += tanhf(a8[3] + b1a.w) * w2a.w;
    dot += tanhf(a8[4] + b1b.x) * w2b.x;
    dot += tanhf(a8[5] + b1b.y) * w2b.y;
    dot += tanhf(a8[6] + b1b.z) * w2b.z;
    dot += tanhf(a8[7] + b1b.w) * w2b.w;
#pragma unroll
    for (int o = 16; o; o >>= 1) dot += __shfl_xor_sync(0xffffffffu, dot, o);
    if (lane == 0) g_y0[gw] = dot;
}

// ---------------- aggregation 2 + bias + squared-norm reduction ---------------
__global__ void k_agg2norm(const float* __restrict__ b2, int n) {
    __shared__ float sh[8];
    int wib  = threadIdx.x >> 5;
    int lane = threadIdx.x & 31;
    int i    = blockIdx.x * 8 + wib;
    float contrib = 0.f;
    if (i < n) {
        int s = g_rowptr[i], e = g_rowptr[i + 1];
        float acc = 0.f;
        for (int k = s + lane; k < e; k += 32) {
            int2 ad = g_adj[k];
            acc += __int_as_float(ad.y) * g_y0[ad.x];
        }
#pragma unroll
        for (int o = 16; o; o >>= 1) acc += __shfl_xor_sync(0xffffffffu, acc, o);
        float z = acc + b2[0];
        contrib = z * z;
    }
    if (lane == 0) sh[wib] = contrib;
    __syncthreads();
    if (threadIdx.x == 0) {
        float s2 = 0.f;
#pragma unroll
        for (int u = 0; u < 8; u++) s2 += sh[u];
        atomicAdd(&g_norm, s2);
    }
}

__global__ void k_final(float* out) { out[0] = sqrtf(g_norm); }

// ---------------- launch ------------------------------------------------------
extern "C" void kernel_launch(void* const* d_in, const int* in_sizes, int n_in,
                              void* d_out, int out_size) {
    const float* x  = (const float*)d_in[0];
    const int*   ei = (const int*)d_in[1];
    const float* W1 = (const float*)d_in[2];
    const float* b1 = (const float*)d_in[3];
    const float* W2 = (const float*)d_in[4];
    const float* b2 = (const float*)d_in[5];
    float* out = (float*)d_out;

    int n = in_sizes[0] / (2 * DD);
    int e = in_sizes[1] / 2;
    const int* row = ei;
    const int* col = ei + e;

    int nb = (n + 1023) / 1024;

    k_init <<<(n + 255) / 256, 256>>>(n);
    k_count<<<(e + 255) / 256, 256>>>(col, e);
    k_scan1<<<nb, 1024>>>(n);
    k_scan2<<<1, 32>>>(nb);
    k_scan3<<<(n + 255) / 256, 256>>>(n);
    k_fill <<<(e + 255) / 256, 256>>>(row, col, e);

    dim3 ggrid(DD / BN, (n + BM - 1) / BM);
    k_gemm1<<<ggrid, 256>>>(x, W1, n);

    k_agg1y<<<(n + 7) / 8, 256>>>(b1, W2, n);
    k_agg2norm<<<(n + 7) / 8, 256>>>(b2, n);
    k_final<<<1, 1>>>(out);
}

// round 9
// speedup vs baseline: 3.2273x; 1.0081x over previous
#include <cuda_runtime.h>
#include <cuda_fp16.h>
#include <cuda_bf16.h>
#include <math.h>
#include <stdint.h>

#define MAXN 100000
#define MAXE 3200000
#define DD   256          // size_in (output dim of layer 1)
#define DH   128          // DD in half2 units
#define KK2  512          // 2*D (input dim of layer 1)

// ---------------- scratch (device globals) ------------------------------------
__device__ __half2 g_h0h[(size_t)MAXN * DH];   // x @ W1   (fp16 storage)
__device__ float g_y0[MAXN];                   // per-node scalar after layer1+W2
__device__ int   g_deg[MAXN];                  // edge-only degree (self loop implicit)
__device__ float g_dinv[MAXN];
__device__ int   g_rowptr[MAXN + 1];
__device__ int   g_cur[MAXN];
__device__ int2  g_adj[MAXE + MAXN];           // (src, weight-bits) interleaved
__device__ int   g_blksum[256];
__device__ float g_norm;

// ---------------- setup kernels ----------------------------------------------
__global__ void k_count(const int* __restrict__ col, int e) {
    int i = blockIdx.x * blockDim.x + threadIdx.x;
    if (i < e) atomicAdd(&g_deg[col[i]], 1);
}

// scan of (deg+1); also computes dinv
__global__ void k_scan1(int n) {
    __shared__ int sh[1024];
    int i = blockIdx.x * 1024 + threadIdx.x;
    int d = (i < n) ? g_deg[i] : -1;
    int v = d + 1;                      // self loop included
    if (i < n) g_dinv[i] = rsqrtf((float)v);
    sh[threadIdx.x] = v;
    __syncthreads();
    for (int off = 1; off < 1024; off <<= 1) {
        int t = (threadIdx.x >= off) ? sh[threadIdx.x - off] : 0;
        __syncthreads();
        sh[threadIdx.x] += t;
        __syncthreads();
    }
    if (i < n) g_rowptr[i + 1] = sh[threadIdx.x];
    if (threadIdx.x == 1023) g_blksum[blockIdx.x] = sh[1023];
}

// parallel exclusive scan of block sums (nb <= 128)
__global__ void k_scan2(int nb) {
    __shared__ int sh[128];
    int t = threadIdx.x;
    int v = (t < nb) ? g_blksum[t] : 0;
    sh[t] = v;
    __syncthreads();
    for (int off = 1; off < 128; off <<= 1) {
        int u = (t >= off) ? sh[t - off] : 0;
        __syncthreads();
        sh[t] += u;
        __syncthreads();
    }
    if (t < nb) g_blksum[t] = sh[t] - v;   // exclusive
    if (t == 0) g_norm = 0.f;
}

// finalize rowptr, write self-loop entry, init cursor
__global__ void k_scan3(int n) {
    int i = blockIdx.x * blockDim.x + threadIdx.x;
    if (i < n) {
        int rp1 = g_rowptr[i + 1] + g_blksum[i >> 10];
        g_rowptr[i + 1] = rp1;
        int cnt = g_deg[i] + 1;
        int p = rp1 - cnt;              // == rowptr[i]
        float di = g_dinv[i];
        g_adj[p] = make_int2(i, __float_as_int(di * di));
        g_cur[i] = p + 1;
    }
    if (i == 0) g_rowptr[0] = 0;
}

__global__ void k_fill(const int* __restrict__ row, const int* __restrict__ col, int e) {
    int i = blockIdx.x * blockDim.x + threadIdx.x;
    if (i < e) {
        int r = row[i], c = col[i];
        int p = atomicAdd(&g_cur[c], 1);
        g_adj[p] = make_int2(r, __float_as_int(g_dinv[r] * g_dinv[c]));
    }
}

// ---------------- GEMM1 (tensor core, bf16 mma, fp32 accum) -------------------
#define BM 128
#define BN 128
#define BK 32

__device__ __forceinline__ uint32_t smem_u32(const void* p) {
    return (uint32_t)__cvta_generic_to_shared(p);
}

__device__ __forceinline__ void ldm_x4(uint32_t& r0, uint32_t& r1, uint32_t& r2, uint32_t& r3,
                                       uint32_t addr) {
    asm volatile("ldmatrix.sync.aligned.m8n8.x4.shared.b16 {%0,%1,%2,%3}, [%4];"
                 : "=r"(r0), "=r"(r1), "=r"(r2), "=r"(r3) : "r"(addr));
}
__device__ __forceinline__ void ldm_x4_t(uint32_t& r0, uint32_t& r1, uint32_t& r2, uint32_t& r3,
                                         uint32_t addr) {
    asm volatile("ldmatrix.sync.aligned.m8n8.x4.trans.shared.b16 {%0,%1,%2,%3}, [%4];"
                 : "=r"(r0), "=r"(r1), "=r"(r2), "=r"(r3) : "r"(addr));
}
__device__ __forceinline__ void mma16816(float* c, const uint32_t* a, uint32_t b0, uint32_t b1) {
    asm volatile("mma.sync.aligned.m16n8k16.row.col.f32.bf16.bf16.f32 "
                 "{%0,%1,%2,%3}, {%4,%5,%6,%7}, {%8,%9}, {%0,%1,%2,%3};"
                 : "+f"(c[0]), "+f"(c[1]), "+f"(c[2]), "+f"(c[3])
                 : "r"(a[0]), "r"(a[1]), "r"(a[2]), "r"(a[3]), "r"(b0), "r"(b1));
}

__global__ __launch_bounds__(256, 1) void k_gemm1(const float* __restrict__ A,
                                                  const float* __restrict__ B, int M) {
    __shared__ __nv_bfloat16 As[2][BM][BK + 8];
    __shared__ __nv_bfloat16 Bs[2][BK][BN + 8];

    int tid  = threadIdx.x;
    int wid  = tid >> 5, lane = tid & 31;
    int wm   = wid & 3;
    int wn   = wid >> 2;
    int rowBase = blockIdx.y * BM;
    int colBase = blockIdx.x * BN;

    int arow = tid >> 1;
    int acol = (tid & 1) * 16;
    int grA  = rowBase + arow;
    bool okA = (grA < M);
    const float4* A4 = (const float4*)A;
    size_t aBase = (size_t)(okA ? grA : 0) * (KK2 / 4);

    int bkr = tid >> 3;
    int bf4 = tid & 7;
    const float4* B4 = (const float4*)B;

    float acc[2][8][4];
#pragma unroll
    for (int mi = 0; mi < 2; mi++)
#pragma unroll
        for (int ni = 0; ni < 8; ni++)
#pragma unroll
            for (int q = 0; q < 4; q++) acc[mi][ni][q] = 0.f;

    float4 ra[4], rb[4];

    auto loadG = [&](int k0) {
        float4 z = make_float4(0.f, 0.f, 0.f, 0.f);
#pragma unroll
        for (int j = 0; j < 4; j++)
            ra[j] = okA ? A4[aBase + ((k0 + acol) >> 2) + j] : z;
#pragma unroll
        for (int j = 0; j < 4; j++)
            rb[j] = B4[(size_t)(k0 + bkr) * (DD / 4) + (colBase >> 2) + bf4 + j * 8];
    };
    auto storeS = [&](int buf) {
        __nv_bfloat162 pa[8];
#pragma unroll
        for (int j = 0; j < 4; j++) {
            pa[2 * j]     = __float22bfloat162_rn(make_float2(ra[j].x, ra[j].y));
            pa[2 * j + 1] = __float22bfloat162_rn(make_float2(ra[j].z, ra[j].w));
        }
        *(uint4*)&As[buf][arow][acol]     = ((uint4*)pa)[0];
        *(uint4*)&As[buf][arow][acol + 8] = ((uint4*)pa)[1];
#pragma unroll
        for (int j = 0; j < 4; j++) {
            __nv_bfloat162 pb[2];
            pb[0] = __float22bfloat162_rn(make_float2(rb[j].x, rb[j].y));
            pb[1] = __float22bfloat162_rn(make_float2(rb[j].z, rb[j].w));
            *(uint2*)&Bs[buf][bkr][(bf4 + j * 8) * 4] = *(uint2*)pb;
        }
    };

    loadG(0);
    storeS(0);
    __syncthreads();

    const int NT = KK2 / BK;
    for (int t = 0; t < NT; t++) {
        int buf = t & 1;
        // prefetch next tile into registers (lands while we compute)
        if (t + 1 < NT) loadG((t + 1) * BK);

        // compute current tile: 2 k16 steps
#pragma unroll
        for (int ks = 0; ks < 2; ks++) {
            uint32_t afr[2][4];
#pragma unroll
            for (int mi = 0; mi < 2; mi++) {
                uint32_t ad = smem_u32(&As[buf][wm * 32 + mi * 16 + (lane & 15)]
                                          [ks * 16 + (lane >> 4) * 8]);
                ldm_x4(afr[mi][0], afr[mi][1], afr[mi][2], afr[mi][3], ad);
            }
#pragma unroll
            for (int p = 0; p < 4; p++) {
                uint32_t b0, b1, b2, b3;
                uint32_t bd = smem_u32(&Bs[buf][ks * 16 + (lane & 15)]
                                          [wn * 64 + p * 16 + (lane >> 4) * 8]);
                ldm_x4_t(b0, b1, b2, b3, bd);
                mma16816(acc[0][2 * p],     afr[0], b0, b1);
                mma16816(acc[1][2 * p],     afr[1], b0, b1);
                mma16816(acc[0][2 * p + 1], afr[0], b2, b3);
                mma16816(acc[1][2 * p + 1], afr[1], b2, b3);
            }
        }
        // write next tile into the other buffer (safe: the barrier below
        // drained all readers of buf^1 last iteration; compute only reads buf).
        if (t + 1 < NT) storeS(buf ^ 1);
        __syncthreads();
    }

#pragma unroll
    for (int mi = 0; mi < 2; mi++) {
#pragma unroll
        for (int ni = 0; ni < 8; ni++) {
            int r0 = rowBase + wm * 32 + mi * 16 + (lane >> 2);
            int c  = colBase + wn * 64 + ni * 8 + (lane & 3) * 2;
            if (r0 < M)
                g_h0h[(size_t)r0 * DH + (c >> 1)] =
                    __floats2half2_rn(acc[mi][ni][0], acc[mi][ni][1]);
            int r1 = r0 + 8;
            if (r1 < M)
                g_h0h[(size_t)r1 * DH + (c >> 1)] =
                    __floats2half2_rn(acc[mi][ni][2], acc[mi][ni][3]);
        }
    }
}

// ---------------- fused aggregation1 + bias + tanh + W2 dot -------------------
__device__ __forceinline__ void acc_row(float* a8, uint4 v, float wt) {
    __half2* h = (__half2*)&v;
#pragma unroll
    for (int q = 0; q < 4; q++) {
        float2 f = __half22float2(h[q]);
        a8[2 * q]     += wt * f.x;
        a8[2 * q + 1] += wt * f.y;
    }
}

__global__ __launch_bounds__(256) void k_agg1y(const float* __restrict__ b1,
                                               const float* __restrict__ W2, int n) {
    int gw   = (blockIdx.x * blockDim.x + threadIdx.x) >> 5;
    int lane = threadIdx.x & 31;
    if (gw >= n) return;
    int s = g_rowptr[gw], e = g_rowptr[gw + 1];

    const uint4* base = (const uint4*)g_h0h;   // 32 uint4 per node row

    float a8[8];
#pragma unroll
    for (int q = 0; q < 8; q++) a8[q] = 0.f;

    int k = s;
#pragma unroll 1
    for (; k + 8 <= e; k += 8) {
        int2 ad[8];
#pragma unroll
        for (int u = 0; u < 8; u++) ad[u] = g_adj[k + u];
        uint4 v[8];
#pragma unroll
        for (int u = 0; u < 8; u++) v[u] = base[(size_t)ad[u].x * 32 + lane];
#pragma unroll
        for (int u = 0; u < 8; u++) acc_row(a8, v[u], __int_as_float(ad[u].y));
    }
    for (; k < e; k++) {
        int2 ad = g_adj[k];
        acc_row(a8, base[(size_t)ad.x * 32 + lane], __int_as_float(ad.y));
    }

    float4 b1a = ((const float4*)b1)[lane * 2];
    float4 b1b = ((const float4*)b1)[lane * 2 + 1];
    float4 w2a = ((const float4*)W2)[lane * 2];
    float4 w2b = ((const float4*)W2)[lane * 2 + 1];
    float dot = 0.f;
    dot += tanhf(a8[0] + b1a.x) * w2a.x;
    dot += tanhf(a8[1] + b1a.y) * w2a.y;
    dot += tanhf(a8[2] + b1a.z) * w2a.z;
    dot += tanhf(a8[3] + b1a.w) * w2a.w;
    dot += tanhf(a8[4] + b1b.x) * w2b.x;
    dot += tanhf(a8[5] + b1b.y) * w2b.y;
    dot += tanhf(a8[6] + b1b.z) * w2b.z;
    dot += tanhf(a8[7] + b1b.w) * w2b.w;
#pragma unroll
    for (int o = 16; o; o >>= 1) dot += __shfl_xor_sync(0xffffffffu, dot, o);
    if (lane == 0) g_y0[gw] = dot;
}

// ---------------- aggregation 2 + bias + squared-norm reduction ---------------
__global__ void k_agg2norm(const float* __restrict__ b2, int n) {
    __shared__ float sh[8];
    int wib  = threadIdx.x >> 5;
    int lane = threadIdx.x & 31;
    int i    = blockIdx.x * 8 + wib;
    float contrib = 0.f;
    if (i < n) {
        int s = g_rowptr[i], e = g_rowptr[i + 1];
        float acc = 0.f;
        for (int k = s + lane; k < e; k += 32) {
            int2 ad = g_adj[k];
            acc += __int_as_float(ad.y) * g_y0[ad.x];
        }
#pragma unroll
        for (int o = 16; o; o >>= 1) acc += __shfl_xor_sync(0xffffffffu, acc, o);
        float z = acc + b2[0];
        contrib = z * z;
    }
    if (lane == 0) sh[wib] = contrib;
    __syncthreads();
    if (threadIdx.x == 0) {
        float s2 = 0.f;
#pragma unroll
        for (int u = 0; u < 8; u++) s2 += sh[u];
        atomicAdd(&g_norm, s2);
    }
}

__global__ void k_final(float* out) { out[0] = sqrtf(g_norm); }

// ---------------- launch ------------------------------------------------------
extern "C" void kernel_launch(void* const* d_in, const int* in_sizes, int n_in,
                              void* d_out, int out_size) {
    const float* x  = (const float*)d_in[0];
    const int*   ei = (const int*)d_in[1];
    const float* W1 = (const float*)d_in[2];
    const float* b1 = (const float*)d_in[3];
    const float* W2 = (const float*)d_in[4];
    const float* b2 = (const float*)d_in[5];
    float* out = (float*)d_out;

    int n = in_sizes[0] / (2 * DD);
    int e = in_sizes[1] / 2;
    const int* row = ei;
    const int* col = ei + e;

    int nb = (n + 1023) / 1024;

    // zero degree array via memset node (capturable, no kernel launch)
    void* degPtr = nullptr;
    cudaGetSymbolAddress(&degPtr, g_deg);
    cudaMemsetAsync(degPtr, 0, (size_t)n * sizeof(int), 0);

    k_count<<<(e + 255) / 256, 256>>>(col, e);
    k_scan1<<<nb, 1024>>>(n);
    k_scan2<<<1, 128>>>(nb);
    k_scan3<<<(n + 255) / 256, 256>>>(n);
    k_fill <<<(e + 255) / 256, 256>>>(row, col, e);

    dim3 ggrid(DD / BN, (n + BM - 1) / BM);
    k_gemm1<<<ggrid, 256>>>(x, W1, n);

    k_agg1y<<<(n + 7) / 8, 256>>>(b1, W2, n);
    k_agg2norm<<<(n + 7) / 8, 256>>>(b2, n);
    k_final<<<1, 1>>>(out);
}